// round 13
// baseline (speedup 1.0000x reference)
#include <cuda_runtime.h>
#include <cuda_fp16.h>
#include <cstdint>

#define B_    32
#define CIN_  256
#define MID_  64
#define EMB_  64
#define H_    112
#define W_    112
#define HW_   (H_*W_)        // 12544
#define EPS_  1e-5f
#define OUT_MAIN_ ((size_t)B_*CIN_*HW_)

#define PR_   114
#define PC_   120
__device__ uint32_t g_t1p2[(size_t)B_*32*PR_*PC_];   // half2 words, padded
__device__ uint32_t g_t2p2[(size_t)B_*32*HW_];       // half2 words [b][kp][hw]
__device__ float g_gate[B_*MID_];

__device__ uint2 g_w1b[16 * 8 * 32];        // [kchunk16][n8=8(oc64)][lane]  B-frag
__device__ uint4 g_w3a[4 * 16 * 32];        // [kchunk4][mb16(oc256)][lane]  A-frag
__device__ uint2 g_w2b[4 * 9 * 8 * 32];     // [icchunk4][tap9][n8=8][lane]  B-frag

__device__ __forceinline__ uint32_t pack2(float lo, float hi) {
    __half2 h = __floats2half2_rn(lo, hi);
    return *(uint32_t*)&h;
}
__device__ __forceinline__ uint32_t sa(const void* p) {
    return (uint32_t)__cvta_generic_to_shared(p);
}
__device__ __forceinline__ void cp16(uint32_t dst, const void* src) {
    asm volatile("cp.async.ca.shared.global [%0], [%1], 16;\n" :: "r"(dst), "l"(src));
}
__device__ __forceinline__ void cp16s(uint32_t dst, const void* src) {
    asm volatile("cp.async.cg.shared.global [%0], [%1], 16;\n" :: "r"(dst), "l"(src));
}
__device__ __forceinline__ void cpcommit() {
    asm volatile("cp.async.commit_group;\n");
}
#define CPWAIT(n) asm volatile("cp.async.wait_group %0;\n" :: "n"(n) : "memory")

__device__ __forceinline__ void mma_f16(float* c, uint32_t a0, uint32_t a1,
                                        uint32_t a2, uint32_t a3,
                                        uint32_t b0, uint32_t b1) {
    asm volatile(
        "mma.sync.aligned.m16n8k16.row.col.f32.f16.f16.f32 "
        "{%0,%1,%2,%3}, {%4,%5,%6,%7}, {%8,%9}, {%0,%1,%2,%3};"
        : "+f"(c[0]), "+f"(c[1]), "+f"(c[2]), "+f"(c[3])
        : "r"(a0), "r"(a1), "r"(a2), "r"(a3), "r"(b0), "r"(b1));
}

// ---------------------------------------------------------------------------
__global__ void prep_kernel(const float* __restrict__ w1,
                            const float* __restrict__ w2,
                            const float* __restrict__ w3) {
    int s = blockIdx.x * blockDim.x + threadIdx.x;   // 0..9215
    if (s >= 9216) return;
    int lane = s & 31;
    int g = lane >> 2, t4 = lane & 3;
    if (s < 4096) {     // w1 (B-frag): [ch16][nb8][lane]
        int nb = (s >> 5) & 7, ch = s >> 8;
        int oc = nb * 8 + g, k0 = ch * 16 + 2 * t4;
        const float* wp = w1 + oc * CIN_ + k0;
        uint2 v;
        v.x = pack2(wp[0], wp[1]);
        v.y = pack2(wp[8], wp[9]);
        g_w1b[s] = v;
    }
    if (s < 2048) {     // w3 (A-frag): [ch4][mb16][lane]
        int mb = (s >> 5) & 15, ch = s >> 9;
        int row = mb * 16 + g, k0 = ch * 16 + 2 * t4;
        uint4 v;
        v.x = pack2(w3[row * MID_ + k0],           w3[row * MID_ + k0 + 1]);
        v.y = pack2(w3[(row + 8) * MID_ + k0],     w3[(row + 8) * MID_ + k0 + 1]);
        v.z = pack2(w3[row * MID_ + k0 + 8],       w3[row * MID_ + k0 + 9]);
        v.w = pack2(w3[(row + 8) * MID_ + k0 + 8], w3[(row + 8) * MID_ + k0 + 9]);
        g_w3a[s] = v;
    }
    {                   // w2 (B-frag): [ch4][tap9][nb8][lane]
        int nb = (s >> 5) & 7;
        int tap = (s % 2304) >> 8;
        int ch = s / 2304;
        int oc = nb * 8 + g, ic0 = ch * 16 + 2 * t4;
        const float* wp = w2 + ((size_t)oc * MID_ + ic0) * 9 + tap;
        uint2 v;
        v.x = pack2(wp[0], wp[9]);
        v.y = pack2(wp[8 * 9], wp[9 * 9]);
        g_w2b[s] = v;
    }
}

// ---------------------------------------------------------------------------
__global__ void gate_kernel(const float* __restrict__ emb,
                            const float* __restrict__ gw,
                            const float* __restrict__ gb,
                            float* __restrict__ out_tail) {
    int idx = blockIdx.x * blockDim.x + threadIdx.x;
    if (idx >= B_ * MID_) return;
    int b = idx / MID_, c = idx % MID_;
    const float* e = emb + b * EMB_;
    const float* w = gw + c * EMB_;
    float acc = gb[c];
#pragma unroll 8
    for (int k = 0; k < EMB_; k++) acc = fmaf(e[k], w[k], acc);
    acc = fmaxf(acc, 0.f);
    g_gate[idx] = acc;
    out_tail[idx] = acc;
}

// ---------------------------------------------------------------------------
// conv1: M=256px, N=64oc, K=256. 5-buffer / 4-in-flight cp.async pipeline
// (dyn smem 93440B). grid (49, 16) per half.
// ---------------------------------------------------------------------------
__global__ __launch_bounds__(256) void conv1_kernel(
    const float* __restrict__ x,
    const float* __restrict__ bg, const float* __restrict__ bb,
    const float* __restrict__ bm, const float* __restrict__ bv,
    int bbase) {
    extern __shared__ char dsm[];
    float (*Xs)[16][260] = (float(*)[16][260])dsm;              // 5 x 16640
    uint2 (*Wb)[8][32]   = (uint2(*)[8][32])(dsm + 83200);      // 5 x 2048
    const int b   = blockIdx.y + bbase;
    const int p0  = blockIdx.x * 256;
    const int tid = threadIdx.x;
    const int lane = tid & 31, w = tid >> 5;
    const int g = lane >> 2, t4 = lane & 3;
    const int pw = w * 32;
    const float* xb = x + (size_t)b * CIN_ * HW_ + p0;

    float c[2][8][4];
#pragma unroll
    for (int mi = 0; mi < 2; mi++)
#pragma unroll
        for (int nb = 0; nb < 8; nb++)
#pragma unroll
            for (int q = 0; q < 4; q++) c[mi][nb][q] = 0.f;

    auto stage = [&](int ch) {
        int buf = ch % 5;
        if (tid < 128)
            cp16(sa(((uint2*)Wb[buf]) + tid * 2), g_w1b + ch * 256 + tid * 2);
#pragma unroll
        for (int i = 0; i < 4; i++) {
            int e4 = tid + i * 256;
            int kk = e4 >> 6, c4 = e4 & 63;
            cp16s(sa(&Xs[buf][kk][c4 * 4]),
                  xb + (size_t)(ch * 16 + kk) * HW_ + c4 * 4);
        }
        cpcommit();
    };

    stage(0); stage(1); stage(2); stage(3);

    for (int ch = 0; ch < 16; ch++) {
        const int buf = ch % 5;
        const int pend = (ch + 4 <= 16 ? ch + 4 : 16) - ch;
        if (pend >= 4)      { CPWAIT(3); }
        else if (pend == 3) { CPWAIT(2); }
        else if (pend == 2) { CPWAIT(1); }
        else                { CPWAIT(0); }
        __syncthreads();
        if (ch + 4 < 16) stage(ch + 4);

        uint32_t a[2][4];
#pragma unroll
        for (int mi = 0; mi < 2; mi++) {
            int p = pw + mi * 16 + g;
            a[mi][0] = pack2(Xs[buf][2*t4][p],     Xs[buf][2*t4+1][p]);
            a[mi][1] = pack2(Xs[buf][2*t4][p+8],   Xs[buf][2*t4+1][p+8]);
            a[mi][2] = pack2(Xs[buf][2*t4+8][p],   Xs[buf][2*t4+9][p]);
            a[mi][3] = pack2(Xs[buf][2*t4+8][p+8], Xs[buf][2*t4+9][p+8]);
        }
#pragma unroll
        for (int nb = 0; nb < 8; nb++) {
            uint2 bf = Wb[buf][nb][lane];
#pragma unroll
            for (int mi = 0; mi < 2; mi++)
                mma_f16(c[mi][nb], a[mi][0], a[mi][1], a[mi][2], a[mi][3],
                        bf.x, bf.y);
        }
    }
#pragma unroll
    for (int nb = 0; nb < 8; nb++) {
        int oc = nb * 8 + 2 * t4;
        float ie = rsqrtf(bv[oc] + EPS_) * bg[oc];
        float be = bb[oc] - bm[oc] * ie;
        float io = rsqrtf(bv[oc+1] + EPS_) * bg[oc+1];
        float bo = bb[oc+1] - bm[oc+1] * io;
        uint32_t* base = g_t1p2 + (size_t)(b * 32 + nb * 4 + t4) * PR_ * PC_;
#pragma unroll
        for (int mi = 0; mi < 2; mi++) {
#pragma unroll
            for (int h = 0; h < 2; h++) {
                int p = p0 + pw + mi * 16 + g + h * 8;
                int y = p / W_, xx = p % W_;
                float ve = fmaxf(fmaf(c[mi][nb][2*h],   ie, be), 0.f);
                float vo = fmaxf(fmaf(c[mi][nb][2*h+1], io, bo), 0.f);
                base[(size_t)(y + 1) * PC_ + xx + 1] = pack2(ve, vo);
            }
        }
    }
}

// ---------------------------------------------------------------------------
// conv2: tensor-bound, unchanged. grid (7,7,16) per half.
// ---------------------------------------------------------------------------
__global__ __launch_bounds__(256) void conv2_kernel(
    const float* __restrict__ bg, const float* __restrict__ bb,
    const float* __restrict__ bm, const float* __restrict__ bv,
    int bbase) {
    extern __shared__ char dsm[];
    uint2    (*Wb)[9][8][32] = (uint2(*)[9][8][32])dsm;                // 2x18432
    uint32_t (*Xh)           = (uint32_t*)(dsm + 36864);               // 2x14080
    const int b   = blockIdx.z + bbase;
    const int ry0 = blockIdx.y * 16;
    const int cx0 = blockIdx.x * 16;
    const int tid = threadIdx.x;
    const int lane = tid & 31, w = tid >> 5;
    const int g = lane >> 2, t4 = lane & 3;
    const int ICS = 440;

    float c[2][8][4];
#pragma unroll
    for (int mi = 0; mi < 2; mi++)
#pragma unroll
        for (int nb = 0; nb < 8; nb++)
#pragma unroll
            for (int q = 0; q < 4; q++) c[mi][nb][q] = 0.f;

    auto stage = [&](int ch, int buf) {
#pragma unroll
        for (int i = 0; i < 5; i++) {
            int e = tid + i * 256;
            if (e < 1152)
                cp16(sa(((uint2*)Wb[buf]) + e * 2), g_w2b + ch * 2304 + e * 2);
        }
        uint32_t* hb = Xh + buf * 3520;
#pragma unroll
        for (int i = 0; i < 4; i++) {
            int e = tid + i * 256;
            if (e < 864) {
                int icp = e / 108, rem = e % 108;
                int r = rem / 6, c6 = rem % 6;
                const uint32_t* src = g_t1p2 +
                    ((size_t)(b * 32 + ch * 8 + icp) * PR_ + ry0 + r) * PC_
                    + cx0 + c6 * 4;
                cp16s(sa(hb + icp * ICS + r * 24 + c6 * 4), src);
            }
        }
        cpcommit();
    };

    stage(0, 0);
    CPWAIT(0);
    __syncthreads();

    for (int ch = 0; ch < 4; ch++) {
        const int cur = ch & 1;
        if (ch + 1 < 4) stage(ch + 1, cur ^ 1);
        const uint32_t* hb = Xh + cur * 3520;
#pragma unroll
        for (int t = 0; t < 9; t++) {
            const int ky = t / 3, kx = t % 3;
            uint2 bf[8];
#pragma unroll
            for (int nb = 0; nb < 8; nb++) bf[nb] = Wb[cur][t][nb][lane];
#pragma unroll
            for (int mi = 0; mi < 2; mi++) {
                int r = 2 * w + mi + ky;
                const uint32_t* h0 = hb + t4 * ICS + r * 24 + g + kx;
                const uint32_t* h1 = hb + (t4 + 4) * ICS + r * 24 + g + kx;
                uint32_t a0 = h0[0], a1 = h0[8], a2 = h1[0], a3 = h1[8];
#pragma unroll
                for (int nb = 0; nb < 8; nb++)
                    mma_f16(c[mi][nb], a0, a1, a2, a3, bf[nb].x, bf[nb].y);
            }
        }
        CPWAIT(0);
        __syncthreads();
    }
#pragma unroll
    for (int nb = 0; nb < 8; nb++) {
        int oc = nb * 8 + 2 * t4;
        float ge = g_gate[b * MID_ + oc];
        float go = g_gate[b * MID_ + oc + 1];
        float ie = rsqrtf(bv[oc] + EPS_) * bg[oc];
        float be = bb[oc] - bm[oc] * ie;
        float io = rsqrtf(bv[oc+1] + EPS_) * bg[oc+1];
        float bo = bb[oc+1] - bm[oc+1] * io;
        uint32_t* base = g_t2p2 + (size_t)(b * 32 + nb * 4 + t4) * HW_;
#pragma unroll
        for (int mi = 0; mi < 2; mi++) {
            int y = ry0 + 2 * w + mi;
#pragma unroll
            for (int h = 0; h < 2; h++) {
                int xx = cx0 + g + h * 8;
                float ve = fmaxf(fmaf(c[mi][nb][2*h]   * ge, ie, be), 0.f);
                float vo = fmaxf(fmaf(c[mi][nb][2*h+1] * go, io, bo), 0.f);
                base[y * W_ + xx] = pack2(ve, vo);
            }
        }
    }
}

// ---------------------------------------------------------------------------
// conv3 (swapped roles): M=256oc, N=32px, K=64. A=w3 frags, B=packed t2.
// C cols = adjacent px -> float2 stores + float2 identity.
// 8 warps = 4 ocgrp x 2 pxgrp (warp m64 x n16). All K staged up-front;
// identity (32KB fp32, stride-40 rows) streamed under MMA.
// dyn smem 78848B. grid (392, 16) per half.
// ---------------------------------------------------------------------------
__global__ __launch_bounds__(256) void conv3_kernel(
    const float* __restrict__ x,
    const float* __restrict__ bg, const float* __restrict__ bb,
    const float* __restrict__ bm, const float* __restrict__ bv,
    float* __restrict__ out, int bbase) {
    extern __shared__ char dsm[];
    uint4    (*Wa)[16][32] = (uint4(*)[16][32])dsm;              // 4x8192 = 32768
    uint32_t (*A2)[8][40]  = (uint32_t(*)[8][40])(dsm + 32768);  // 4x1280 = 5120
    float*   Xid           = (float*)(dsm + 37888);              // 256 x 40 x 4
    const int b   = blockIdx.y + bbase;
    const int p0  = blockIdx.x * 32;
    const int tid = threadIdx.x;
    const int lane = tid & 31, w = tid >> 5;
    const int ocg = w >> 1, pxg = w & 1;
    const int g = lane >> 2, t4 = lane & 3;
    const uint32_t* t2b = g_t2p2 + (size_t)b * 32 * HW_ + p0;
    const float* xg = x + (size_t)b * CIN_ * HW_ + p0;

    float c[4][2][4];
#pragma unroll
    for (int mi = 0; mi < 4; mi++)
#pragma unroll
        for (int nb = 0; nb < 2; nb++)
#pragma unroll
            for (int q = 0; q < 4; q++) c[mi][nb][q] = 0.f;

    // group 0: all weights + all t2
    {
        // Wa: 2048 uint4, 8/thread
#pragma unroll
        for (int i = 0; i < 8; i++) {
            int e = tid + i * 256;
            cp16(sa(((uint4*)Wa) + e), g_w3a + e);
        }
        // A2: 4ch x 8kp x 32px = 256 cp16, 1/thread
        int ch = tid >> 6, kp = (tid >> 3) & 7, c8 = tid & 7;
        cp16s(sa(&A2[ch][kp][c8 * 4]),
              t2b + (size_t)(ch * 8 + kp) * HW_ + c8 * 4);
        cpcommit();
    }
    // groups 1..4: identity 256oc x 32px, 2048 cp16 total
#pragma unroll
    for (int grp = 0; grp < 4; grp++) {
#pragma unroll
        for (int i = 0; i < 2; i++) {
            int e = tid + (grp * 2 + i) * 256;   // 0..2047
            int oc = e >> 3, c8 = e & 7;
            cp16s(sa(Xid + oc * 40 + c8 * 4),
                  xg + (size_t)oc * HW_ + c8 * 4);
        }
        cpcommit();
    }

    CPWAIT(4);            // weights + t2 ready; identity still streaming
    __syncthreads();

#pragma unroll
    for (int ch = 0; ch < 4; ch++) {
        uint4 af[4];
#pragma unroll
        for (int mi = 0; mi < 4; mi++)
            af[mi] = Wa[ch][ocg * 4 + mi][lane];
#pragma unroll
        for (int nb = 0; nb < 2; nb++) {
            int pxl = pxg * 16 + nb * 8 + g;
            uint32_t b0 = A2[ch][t4][pxl];
            uint32_t b1 = A2[ch][t4 + 4][pxl];
#pragma unroll
            for (int mi = 0; mi < 4; mi++)
                mma_f16(c[mi][nb], af[mi].x, af[mi].y, af[mi].z, af[mi].w,
                        b0, b1);
        }
    }

    CPWAIT(0);            // identity landed
    __syncthreads();

    // epilogue: bn + identity (smem, float2) + relu, float2 stores
#pragma unroll
    for (int mi = 0; mi < 4; mi++) {
        int ocl = ocg * 64 + mi * 16 + g;
#pragma unroll
        for (int r = 0; r < 2; r++) {
            int oc = ocl + r * 8;
            float iv = rsqrtf(bv[oc] + EPS_) * bg[oc];
            float bs = bb[oc] - bm[oc] * iv;
            float* op = out + ((size_t)b * CIN_ + oc) * HW_ + p0;
            const float* sp = Xid + oc * 40;
#pragma unroll
            for (int nb = 0; nb < 2; nb++) {
                int px = pxg * 16 + nb * 8 + 2 * t4;
                float2 id = *(const float2*)&sp[px];
                float2 v;
                v.x = fmaxf(fmaf(c[mi][nb][2*r],     iv, bs) + id.x, 0.f);
                v.y = fmaxf(fmaf(c[mi][nb][2*r + 1], iv, bs) + id.y, 0.f);
                *(float2*)&op[px] = v;
            }
        }
    }
}

// ---------------------------------------------------------------------------
static cudaStream_t g_s1 = nullptr;
static cudaEvent_t  g_evA = nullptr, g_evB = nullptr;
static bool g_pipe_ok = false;
static struct _StreamInit {
    _StreamInit() {
        g_pipe_ok =
            cudaStreamCreateWithFlags(&g_s1, cudaStreamNonBlocking) == cudaSuccess &&
            cudaEventCreateWithFlags(&g_evA, cudaEventDisableTiming) == cudaSuccess &&
            cudaEventCreateWithFlags(&g_evB, cudaEventDisableTiming) == cudaSuccess;
    }
} _stream_init;

extern "C" void kernel_launch(void* const* d_in, const int* in_sizes, int n_in,
                              void* d_out, int out_size) {
    const float* x     = (const float*)d_in[0];
    const float* emb   = (const float*)d_in[1];
    const float* w1    = (const float*)d_in[2];
    const float* bn1_g = (const float*)d_in[3];
    const float* bn1_b = (const float*)d_in[4];
    const float* bn1_m = (const float*)d_in[5];
    const float* bn1_v = (const float*)d_in[6];
    const float* w2    = (const float*)d_in[7];
    const float* bn2_g = (const float*)d_in[8];
    const float* bn2_b = (const float*)d_in[9];
    const float* bn2_m = (const float*)d_in[10];
    const float* bn2_v = (const float*)d_in[11];
    const float* w3    = (const float*)d_in[12];
    const float* bn3_g = (const float*)d_in[13];
    const float* bn3_b = (const float*)d_in[14];
    const float* bn3_m = (const float*)d_in[15];
    const float* bn3_v = (const float*)d_in[16];
    const float* gw    = (const float*)d_in[17];
    const float* gb    = (const float*)d_in[18];
    float* out = (float*)d_out;

    cudaFuncSetAttribute(conv1_kernel,
                         cudaFuncAttributeMaxDynamicSharedMemorySize, 93440);
    cudaFuncSetAttribute(conv2_kernel,
                         cudaFuncAttributeMaxDynamicSharedMemorySize, 65024);
    cudaFuncSetAttribute(conv3_kernel,
                         cudaFuncAttributeMaxDynamicSharedMemorySize, 78848);

    const int HB = B_ / 2;                 // 16 batches per half
    dim3 g1(HW_ / 256, HB);
    dim3 g2(W_ / 16, H_ / 16, HB);
    dim3 g3(HW_ / 32, HB);

    prep_kernel<<<36, 256>>>(w1, w2, w3);
    gate_kernel<<<(B_ * MID_ + 255) / 256, 256>>>(emb, gw, gb, out + OUT_MAIN_);

    if (g_pipe_ok) {
        conv1_kernel<<<g1, 256, 93440>>>(x, bn1_g, bn1_b, bn1_m, bn1_v, 0);
        cudaEventRecord(g_evA, 0);
        cudaStreamWaitEvent(g_s1, g_evA, 0);
        conv1_kernel<<<g1, 256, 93440, g_s1>>>(x, bn1_g, bn1_b, bn1_m, bn1_v, HB);
        conv2_kernel<<<g2, 256, 65024>>>(bn2_g, bn2_b, bn2_m, bn2_v, 0);
        conv2_kernel<<<g2, 256, 65024, g_s1>>>(bn2_g, bn2_b, bn2_m, bn2_v, HB);
        conv3_kernel<<<g3, 256, 78848>>>(x, bn3_g, bn3_b, bn3_m, bn3_v, out, 0);
        conv3_kernel<<<g3, 256, 78848, g_s1>>>(x, bn3_g, bn3_b, bn3_m, bn3_v, out, HB);
        cudaEventRecord(g_evB, g_s1);
        cudaStreamWaitEvent(0, g_evB, 0);
    } else {
        conv1_kernel<<<g1, 256, 93440>>>(x, bn1_g, bn1_b, bn1_m, bn1_v, 0);
        conv1_kernel<<<g1, 256, 93440>>>(x, bn1_g, bn1_b, bn1_m, bn1_v, HB);
        conv2_kernel<<<g2, 256, 65024>>>(bn2_g, bn2_b, bn2_m, bn2_v, 0);
        conv2_kernel<<<g2, 256, 65024>>>(bn2_g, bn2_b, bn2_m, bn2_v, HB);
        conv3_kernel<<<g3, 256, 78848>>>(x, bn3_g, bn3_b, bn3_m, bn3_v, out, 0);
        conv3_kernel<<<g3, 256, 78848>>>(x, bn3_g, bn3_b, bn3_m, bn3_v, out, HB);
    }
}

// round 14
// speedup vs baseline: 1.0584x; 1.0584x over previous
#include <cuda_runtime.h>
#include <cuda_fp16.h>
#include <cstdint>

#define B_    32
#define CIN_  256
#define MID_  64
#define EMB_  64
#define H_    112
#define W_    112
#define HW_   (H_*W_)        // 12544
#define EPS_  1e-5f
#define OUT_MAIN_ ((size_t)B_*CIN_*HW_)

#define PR_   114
#define PC_   120
__device__ uint32_t g_t1p2[(size_t)B_*32*PR_*PC_];   // half2 words, padded
__device__ uint32_t g_t2p2[(size_t)B_*32*HW_];       // half2 words [b][kp][hw]
__device__ float g_gate[B_*MID_];

__device__ uint2 g_w1b[16 * 8 * 32];        // [kchunk16][n8=8(oc64)][lane]  B-frag
__device__ uint4 g_w3a[4 * 16 * 32];        // [kchunk4][mb16(oc256)][lane]  A-frag
__device__ uint2 g_w2b[4 * 9 * 8 * 32];     // [icchunk4][tap9][n8=8][lane]  B-frag

__device__ __forceinline__ uint32_t pack2(float lo, float hi) {
    __half2 h = __floats2half2_rn(lo, hi);
    return *(uint32_t*)&h;
}
__device__ __forceinline__ uint32_t sa(const void* p) {
    return (uint32_t)__cvta_generic_to_shared(p);
}
__device__ __forceinline__ void cp16(uint32_t dst, const void* src) {
    asm volatile("cp.async.ca.shared.global [%0], [%1], 16;\n" :: "r"(dst), "l"(src));
}
__device__ __forceinline__ void cp16s(uint32_t dst, const void* src) {
    asm volatile("cp.async.cg.shared.global [%0], [%1], 16;\n" :: "r"(dst), "l"(src));
}
__device__ __forceinline__ void cpcommit() {
    asm volatile("cp.async.commit_group;\n");
}
#define CPWAIT(n) asm volatile("cp.async.wait_group %0;\n" :: "n"(n) : "memory")

__device__ __forceinline__ void mma_f16(float* c, uint32_t a0, uint32_t a1,
                                        uint32_t a2, uint32_t a3,
                                        uint32_t b0, uint32_t b1) {
    asm volatile(
        "mma.sync.aligned.m16n8k16.row.col.f32.f16.f16.f32 "
        "{%0,%1,%2,%3}, {%4,%5,%6,%7}, {%8,%9}, {%0,%1,%2,%3};"
        : "+f"(c[0]), "+f"(c[1]), "+f"(c[2]), "+f"(c[3])
        : "r"(a0), "r"(a1), "r"(a2), "r"(a3), "r"(b0), "r"(b1));
}

// ---------------------------------------------------------------------------
__global__ void prep_kernel(const float* __restrict__ w1,
                            const float* __restrict__ w2,
                            const float* __restrict__ w3) {
    int s = blockIdx.x * blockDim.x + threadIdx.x;   // 0..9215
    if (s >= 9216) return;
    int lane = s & 31;
    int g = lane >> 2, t4 = lane & 3;
    if (s < 4096) {     // w1 (B-frag): [ch16][nb8][lane]
        int nb = (s >> 5) & 7, ch = s >> 8;
        int oc = nb * 8 + g, k0 = ch * 16 + 2 * t4;
        const float* wp = w1 + oc * CIN_ + k0;
        uint2 v;
        v.x = pack2(wp[0], wp[1]);
        v.y = pack2(wp[8], wp[9]);
        g_w1b[s] = v;
    }
    if (s < 2048) {     // w3 (A-frag): [ch4][mb16][lane]
        int mb = (s >> 5) & 15, ch = s >> 9;
        int row = mb * 16 + g, k0 = ch * 16 + 2 * t4;
        uint4 v;
        v.x = pack2(w3[row * MID_ + k0],           w3[row * MID_ + k0 + 1]);
        v.y = pack2(w3[(row + 8) * MID_ + k0],     w3[(row + 8) * MID_ + k0 + 1]);
        v.z = pack2(w3[row * MID_ + k0 + 8],       w3[row * MID_ + k0 + 9]);
        v.w = pack2(w3[(row + 8) * MID_ + k0 + 8], w3[(row + 8) * MID_ + k0 + 9]);
        g_w3a[s] = v;
    }
    {                   // w2 (B-frag): [ch4][tap9][nb8][lane]
        int nb = (s >> 5) & 7;
        int tap = (s % 2304) >> 8;
        int ch = s / 2304;
        int oc = nb * 8 + g, ic0 = ch * 16 + 2 * t4;
        const float* wp = w2 + ((size_t)oc * MID_ + ic0) * 9 + tap;
        uint2 v;
        v.x = pack2(wp[0], wp[9]);
        v.y = pack2(wp[8 * 9], wp[9 * 9]);
        g_w2b[s] = v;
    }
}

// ---------------------------------------------------------------------------
__global__ void gate_kernel(const float* __restrict__ emb,
                            const float* __restrict__ gw,
                            const float* __restrict__ gb,
                            float* __restrict__ out_tail) {
    int idx = blockIdx.x * blockDim.x + threadIdx.x;
    if (idx >= B_ * MID_) return;
    int b = idx / MID_, c = idx % MID_;
    const float* e = emb + b * EMB_;
    const float* w = gw + c * EMB_;
    float acc = gb[c];
#pragma unroll 8
    for (int k = 0; k < EMB_; k++) acc = fmaf(e[k], w[k], acc);
    acc = fmaxf(acc, 0.f);
    g_gate[idx] = acc;
    out_tail[idx] = acc;
}

// ---------------------------------------------------------------------------
// conv1: M=256px, N=64oc, K=256. 5-buffer / 4-in-flight cp.async pipeline
// (dyn smem 93440B). grid (49, 16) per half.   [unchanged from R12]
// ---------------------------------------------------------------------------
__global__ __launch_bounds__(256) void conv1_kernel(
    const float* __restrict__ x,
    const float* __restrict__ bg, const float* __restrict__ bb,
    const float* __restrict__ bm, const float* __restrict__ bv,
    int bbase) {
    extern __shared__ char dsm[];
    float (*Xs)[16][260] = (float(*)[16][260])dsm;              // 5 x 16640
    uint2 (*Wb)[8][32]   = (uint2(*)[8][32])(dsm + 83200);      // 5 x 2048
    const int b   = blockIdx.y + bbase;
    const int p0  = blockIdx.x * 256;
    const int tid = threadIdx.x;
    const int lane = tid & 31, w = tid >> 5;
    const int g = lane >> 2, t4 = lane & 3;
    const int pw = w * 32;
    const float* xb = x + (size_t)b * CIN_ * HW_ + p0;

    float c[2][8][4];
#pragma unroll
    for (int mi = 0; mi < 2; mi++)
#pragma unroll
        for (int nb = 0; nb < 8; nb++)
#pragma unroll
            for (int q = 0; q < 4; q++) c[mi][nb][q] = 0.f;

    auto stage = [&](int ch) {
        int buf = ch % 5;
        if (tid < 128)
            cp16(sa(((uint2*)Wb[buf]) + tid * 2), g_w1b + ch * 256 + tid * 2);
#pragma unroll
        for (int i = 0; i < 4; i++) {
            int e4 = tid + i * 256;
            int kk = e4 >> 6, c4 = e4 & 63;
            cp16s(sa(&Xs[buf][kk][c4 * 4]),
                  xb + (size_t)(ch * 16 + kk) * HW_ + c4 * 4);
        }
        cpcommit();
    };

    stage(0); stage(1); stage(2); stage(3);

    for (int ch = 0; ch < 16; ch++) {
        const int buf = ch % 5;
        const int pend = (ch + 4 <= 16 ? ch + 4 : 16) - ch;
        if (pend >= 4)      { CPWAIT(3); }
        else if (pend == 3) { CPWAIT(2); }
        else if (pend == 2) { CPWAIT(1); }
        else                { CPWAIT(0); }
        __syncthreads();
        if (ch + 4 < 16) stage(ch + 4);

        uint32_t a[2][4];
#pragma unroll
        for (int mi = 0; mi < 2; mi++) {
            int p = pw + mi * 16 + g;
            a[mi][0] = pack2(Xs[buf][2*t4][p],     Xs[buf][2*t4+1][p]);
            a[mi][1] = pack2(Xs[buf][2*t4][p+8],   Xs[buf][2*t4+1][p+8]);
            a[mi][2] = pack2(Xs[buf][2*t4+8][p],   Xs[buf][2*t4+9][p]);
            a[mi][3] = pack2(Xs[buf][2*t4+8][p+8], Xs[buf][2*t4+9][p+8]);
        }
#pragma unroll
        for (int nb = 0; nb < 8; nb++) {
            uint2 bf = Wb[buf][nb][lane];
#pragma unroll
            for (int mi = 0; mi < 2; mi++)
                mma_f16(c[mi][nb], a[mi][0], a[mi][1], a[mi][2], a[mi][3],
                        bf.x, bf.y);
        }
    }
#pragma unroll
    for (int nb = 0; nb < 8; nb++) {
        int oc = nb * 8 + 2 * t4;
        float ie = rsqrtf(bv[oc] + EPS_) * bg[oc];
        float be = bb[oc] - bm[oc] * ie;
        float io = rsqrtf(bv[oc+1] + EPS_) * bg[oc+1];
        float bo = bb[oc+1] - bm[oc+1] * io;
        uint32_t* base = g_t1p2 + (size_t)(b * 32 + nb * 4 + t4) * PR_ * PC_;
#pragma unroll
        for (int mi = 0; mi < 2; mi++) {
#pragma unroll
            for (int h = 0; h < 2; h++) {
                int p = p0 + pw + mi * 16 + g + h * 8;
                int y = p / W_, xx = p % W_;
                float ve = fmaxf(fmaf(c[mi][nb][2*h],   ie, be), 0.f);
                float vo = fmaxf(fmaf(c[mi][nb][2*h+1], io, bo), 0.f);
                base[(size_t)(y + 1) * PC_ + xx + 1] = pack2(ve, vo);
            }
        }
    }
}

// ---------------------------------------------------------------------------
// conv2: tensor-bound, unchanged. grid (7,7,16) per half.
// ---------------------------------------------------------------------------
__global__ __launch_bounds__(256) void conv2_kernel(
    const float* __restrict__ bg, const float* __restrict__ bb,
    const float* __restrict__ bm, const float* __restrict__ bv,
    int bbase) {
    extern __shared__ char dsm[];
    uint2    (*Wb)[9][8][32] = (uint2(*)[9][8][32])dsm;                // 2x18432
    uint32_t (*Xh)           = (uint32_t*)(dsm + 36864);               // 2x14080
    const int b   = blockIdx.z + bbase;
    const int ry0 = blockIdx.y * 16;
    const int cx0 = blockIdx.x * 16;
    const int tid = threadIdx.x;
    const int lane = tid & 31, w = tid >> 5;
    const int g = lane >> 2, t4 = lane & 3;
    const int ICS = 440;

    float c[2][8][4];
#pragma unroll
    for (int mi = 0; mi < 2; mi++)
#pragma unroll
        for (int nb = 0; nb < 8; nb++)
#pragma unroll
            for (int q = 0; q < 4; q++) c[mi][nb][q] = 0.f;

    auto stage = [&](int ch, int buf) {
#pragma unroll
        for (int i = 0; i < 5; i++) {
            int e = tid + i * 256;
            if (e < 1152)
                cp16(sa(((uint2*)Wb[buf]) + e * 2), g_w2b + ch * 2304 + e * 2);
        }
        uint32_t* hb = Xh + buf * 3520;
#pragma unroll
        for (int i = 0; i < 4; i++) {
            int e = tid + i * 256;
            if (e < 864) {
                int icp = e / 108, rem = e % 108;
                int r = rem / 6, c6 = rem % 6;
                const uint32_t* src = g_t1p2 +
                    ((size_t)(b * 32 + ch * 8 + icp) * PR_ + ry0 + r) * PC_
                    + cx0 + c6 * 4;
                cp16s(sa(hb + icp * ICS + r * 24 + c6 * 4), src);
            }
        }
        cpcommit();
    };

    stage(0, 0);
    CPWAIT(0);
    __syncthreads();

    for (int ch = 0; ch < 4; ch++) {
        const int cur = ch & 1;
        if (ch + 1 < 4) stage(ch + 1, cur ^ 1);
        const uint32_t* hb = Xh + cur * 3520;
#pragma unroll
        for (int t = 0; t < 9; t++) {
            const int ky = t / 3, kx = t % 3;
            uint2 bf[8];
#pragma unroll
            for (int nb = 0; nb < 8; nb++) bf[nb] = Wb[cur][t][nb][lane];
#pragma unroll
            for (int mi = 0; mi < 2; mi++) {
                int r = 2 * w + mi + ky;
                const uint32_t* h0 = hb + t4 * ICS + r * 24 + g + kx;
                const uint32_t* h1 = hb + (t4 + 4) * ICS + r * 24 + g + kx;
                uint32_t a0 = h0[0], a1 = h0[8], a2 = h1[0], a3 = h1[8];
#pragma unroll
                for (int nb = 0; nb < 8; nb++)
                    mma_f16(c[mi][nb], a0, a1, a2, a3, bf[nb].x, bf[nb].y);
            }
        }
        CPWAIT(0);
        __syncthreads();
    }
#pragma unroll
    for (int nb = 0; nb < 8; nb++) {
        int oc = nb * 8 + 2 * t4;
        float ge = g_gate[b * MID_ + oc];
        float go = g_gate[b * MID_ + oc + 1];
        float ie = rsqrtf(bv[oc] + EPS_) * bg[oc];
        float be = bb[oc] - bm[oc] * ie;
        float io = rsqrtf(bv[oc+1] + EPS_) * bg[oc+1];
        float bo = bb[oc+1] - bm[oc+1] * io;
        uint32_t* base = g_t2p2 + (size_t)(b * 32 + nb * 4 + t4) * HW_;
#pragma unroll
        for (int mi = 0; mi < 2; mi++) {
            int y = ry0 + 2 * w + mi;
#pragma unroll
            for (int h = 0; h < 2; h++) {
                int xx = cx0 + g + h * 8;
                float ve = fmaxf(fmaf(c[mi][nb][2*h]   * ge, ie, be), 0.f);
                float vo = fmaxf(fmaf(c[mi][nb][2*h+1] * go, io, bo), 0.f);
                base[y * W_ + xx] = pack2(ve, vo);
            }
        }
    }
}

// ---------------------------------------------------------------------------
// conv3 (swapped roles, R12 tiling): block 128oc x 128px, M=oc, N=px, K=64.
// 8 warps = 2 ocg x 4 pxg (warp m64 x n32). C cols = adjacent px ->
// float2 stores + float2 identity LDS. All K staged up-front; identity
// (64KB fp32, stride-136 rows) streamed under MMA. dyn smem 103424B.
// grid (98, 2, 16) per half.
// ---------------------------------------------------------------------------
__global__ __launch_bounds__(256) void conv3_kernel(
    const float* __restrict__ x,
    const float* __restrict__ bg, const float* __restrict__ bb,
    const float* __restrict__ bm, const float* __restrict__ bv,
    float* __restrict__ out, int bbase) {
    extern __shared__ char dsm[];
    uint4    (*Wa)[8][32]  = (uint4(*)[8][32])dsm;               // 4x4096 = 16384
    uint32_t (*A2)[8][136] = (uint32_t(*)[8][136])(dsm + 16384); // 4x4352 = 17408
    float*   Xid           = (float*)(dsm + 33792);              // 128x136x4 = 69632
    const int b   = blockIdx.z + bbase;
    const int oc0 = blockIdx.y * 128;
    const int p0  = blockIdx.x * 128;
    const int tid = threadIdx.x;
    const int lane = tid & 31, w = tid >> 5;
    const int ocg = w >> 2, pxg = w & 3;
    const int g = lane >> 2, t4 = lane & 3;
    const uint32_t* t2b = g_t2p2 + (size_t)b * 32 * HW_ + p0;
    const float* xg = x + ((size_t)b * CIN_ + oc0) * HW_ + p0;
    const int mb0 = oc0 >> 4;              // 0 or 8

    float c[4][4][4];
#pragma unroll
    for (int mi = 0; mi < 4; mi++)
#pragma unroll
        for (int nb = 0; nb < 4; nb++)
#pragma unroll
            for (int q = 0; q < 4; q++) c[mi][nb][q] = 0.f;

    // group 0: all weights (A-frags) + all t2 (B)
    {
#pragma unroll
        for (int i = 0; i < 4; i++) {
            int e = tid + i * 256;               // 0..1023
            int ch = e >> 8, mb = (e >> 5) & 7, ln = e & 31;
            cp16(sa(&Wa[ch][mb][ln]),
                 g_w3a + ch * 512 + (mb0 + mb) * 32 + ln);
        }
#pragma unroll
        for (int i = 0; i < 4; i++) {
            int e = tid + i * 256;               // 0..1023
            int ch = e >> 8, kp = (e >> 5) & 7, c8 = e & 31;
            cp16s(sa(&A2[ch][kp][c8 * 4]),
                  t2b + (size_t)(ch * 8 + kp) * HW_ + c8 * 4);
        }
        cpcommit();
    }
    // groups 1..4: identity 128oc x 128px fp32, smem row stride 136
#pragma unroll
    for (int grp = 0; grp < 4; grp++) {
#pragma unroll
        for (int i = 0; i < 4; i++) {
            int e = tid + (grp * 4 + i) * 256;   // 0..4095
            int oc = e >> 5, c8 = e & 31;
            cp16s(sa(Xid + oc * 136 + c8 * 4),
                  xg + (size_t)oc * HW_ + c8 * 4);
        }
        cpcommit();
    }

    CPWAIT(4);            // weights + t2 ready; identity still streaming
    __syncthreads();

#pragma unroll
    for (int ch = 0; ch < 4; ch++) {
        uint4 af[4];
#pragma unroll
        for (int mi = 0; mi < 4; mi++)
            af[mi] = Wa[ch][ocg * 4 + mi][lane];
#pragma unroll
        for (int nb = 0; nb < 4; nb++) {
            int pxl = pxg * 32 + nb * 8 + g;
            uint32_t b0 = A2[ch][t4][pxl];
            uint32_t b1 = A2[ch][t4 + 4][pxl];
#pragma unroll
            for (int mi = 0; mi < 4; mi++)
                mma_f16(c[mi][nb], af[mi].x, af[mi].y, af[mi].z, af[mi].w,
                        b0, b1);
        }
    }

    CPWAIT(0);            // identity landed
    __syncthreads();

    // epilogue: bn + identity (smem, float2) + relu, float2 stores
#pragma unroll
    for (int mi = 0; mi < 4; mi++) {
#pragma unroll
        for (int r = 0; r < 2; r++) {
            int ocl = ocg * 64 + mi * 16 + g + r * 8;
            int oc  = oc0 + ocl;
            float iv = rsqrtf(bv[oc] + EPS_) * bg[oc];
            float bs = bb[oc] - bm[oc] * iv;
            float* op = out + ((size_t)b * CIN_ + oc) * HW_ + p0;
            const float* sp = Xid + ocl * 136;
#pragma unroll
            for (int nb = 0; nb < 4; nb++) {
                int px = pxg * 32 + nb * 8 + 2 * t4;
                float2 id = *(const float2*)&sp[px];
                float2 v;
                v.x = fmaxf(fmaf(c[mi][nb][2*r],     iv, bs) + id.x, 0.f);
                v.y = fmaxf(fmaf(c[mi][nb][2*r + 1], iv, bs) + id.y, 0.f);
                *(float2*)&op[px] = v;
            }
        }
    }
}

// ---------------------------------------------------------------------------
static cudaStream_t g_s1 = nullptr;
static cudaEvent_t  g_evA = nullptr, g_evB = nullptr;
static bool g_pipe_ok = false;
static struct _StreamInit {
    _StreamInit() {
        g_pipe_ok =
            cudaStreamCreateWithFlags(&g_s1, cudaStreamNonBlocking) == cudaSuccess &&
            cudaEventCreateWithFlags(&g_evA, cudaEventDisableTiming) == cudaSuccess &&
            cudaEventCreateWithFlags(&g_evB, cudaEventDisableTiming) == cudaSuccess;
    }
} _stream_init;

extern "C" void kernel_launch(void* const* d_in, const int* in_sizes, int n_in,
                              void* d_out, int out_size) {
    const float* x     = (const float*)d_in[0];
    const float* emb   = (const float*)d_in[1];
    const float* w1    = (const float*)d_in[2];
    const float* bn1_g = (const float*)d_in[3];
    const float* bn1_b = (const float*)d_in[4];
    const float* bn1_m = (const float*)d_in[5];
    const float* bn1_v = (const float*)d_in[6];
    const float* w2    = (const float*)d_in[7];
    const float* bn2_g = (const float*)d_in[8];
    const float* bn2_b = (const float*)d_in[9];
    const float* bn2_m = (const float*)d_in[10];
    const float* bn2_v = (const float*)d_in[11];
    const float* w3    = (const float*)d_in[12];
    const float* bn3_g = (const float*)d_in[13];
    const float* bn3_b = (const float*)d_in[14];
    const float* bn3_m = (const float*)d_in[15];
    const float* bn3_v = (const float*)d_in[16];
    const float* gw    = (const float*)d_in[17];
    const float* gb    = (const float*)d_in[18];
    float* out = (float*)d_out;

    cudaFuncSetAttribute(conv1_kernel,
                         cudaFuncAttributeMaxDynamicSharedMemorySize, 93440);
    cudaFuncSetAttribute(conv2_kernel,
                         cudaFuncAttributeMaxDynamicSharedMemorySize, 65024);
    cudaFuncSetAttribute(conv3_kernel,
                         cudaFuncAttributeMaxDynamicSharedMemorySize, 103424);

    const int HB = B_ / 2;                 // 16 batches per half
    dim3 g1(HW_ / 256, HB);
    dim3 g2(W_ / 16, H_ / 16, HB);
    dim3 g3(HW_ / 128, 2, HB);

    prep_kernel<<<36, 256>>>(w1, w2, w3);
    gate_kernel<<<(B_ * MID_ + 255) / 256, 256>>>(emb, gw, gb, out + OUT_MAIN_);

    if (g_pipe_ok) {
        conv1_kernel<<<g1, 256, 93440>>>(x, bn1_g, bn1_b, bn1_m, bn1_v, 0);
        cudaEventRecord(g_evA, 0);
        cudaStreamWaitEvent(g_s1, g_evA, 0);
        conv1_kernel<<<g1, 256, 93440, g_s1>>>(x, bn1_g, bn1_b, bn1_m, bn1_v, HB);
        conv2_kernel<<<g2, 256, 65024>>>(bn2_g, bn2_b, bn2_m, bn2_v, 0);
        conv2_kernel<<<g2, 256, 65024, g_s1>>>(bn2_g, bn2_b, bn2_m, bn2_v, HB);
        conv3_kernel<<<g3, 256, 103424>>>(x, bn3_g, bn3_b, bn3_m, bn3_v, out, 0);
        conv3_kernel<<<g3, 256, 103424, g_s1>>>(x, bn3_g, bn3_b, bn3_m, bn3_v, out, HB);
        cudaEventRecord(g_evB, g_s1);
        cudaStreamWaitEvent(0, g_evB, 0);
    } else {
        conv1_kernel<<<g1, 256, 93440>>>(x, bn1_g, bn1_b, bn1_m, bn1_v, 0);
        conv1_kernel<<<g1, 256, 93440>>>(x, bn1_g, bn1_b, bn1_m, bn1_v, HB);
        conv2_kernel<<<g2, 256, 65024>>>(bn2_g, bn2_b, bn2_m, bn2_v, 0);
        conv2_kernel<<<g2, 256, 65024>>>(bn2_g, bn2_b, bn2_m, bn2_v, HB);
        conv3_kernel<<<g3, 256, 103424>>>(x, bn3_g, bn3_b, bn3_m, bn3_v, out, 0);
        conv3_kernel<<<g3, 256, 103424>>>(x, bn3_g, bn3_b, bn3_m, bn3_v, out, HB);
    }
}

// round 15
// speedup vs baseline: 1.0595x; 1.0010x over previous
#include <cuda_runtime.h>
#include <cuda_fp16.h>
#include <cstdint>

#define B_    32
#define CIN_  256
#define MID_  64
#define EMB_  64
#define H_    112
#define W_    112
#define HW_   (H_*W_)        // 12544
#define EPS_  1e-5f
#define OUT_MAIN_ ((size_t)B_*CIN_*HW_)

#define PR_   114
#define PC_   120
__device__ uint32_t g_t1p2[(size_t)B_*32*PR_*PC_];   // half2 words, padded
__device__ uint32_t g_t2p2[(size_t)B_*32*HW_];       // half2 words [b][kp][hw]
__device__ float g_gate[B_*MID_];

__device__ uint2 g_w1b[16 * 8 * 32];        // [kchunk16][n8=8(oc64)][lane]  B-frag
__device__ uint4 g_w3a[4 * 16 * 32];        // [kchunk4][mb16(oc256)][lane]  A-frag
__device__ uint2 g_w2b[4 * 9 * 8 * 32];     // [icchunk4][tap9][n8=8][lane]  B-frag

__device__ __forceinline__ uint32_t pack2(float lo, float hi) {
    __half2 h = __floats2half2_rn(lo, hi);
    return *(uint32_t*)&h;
}
__device__ __forceinline__ uint32_t sa(const void* p) {
    return (uint32_t)__cvta_generic_to_shared(p);
}
__device__ __forceinline__ void cp16(uint32_t dst, const void* src) {
    asm volatile("cp.async.ca.shared.global [%0], [%1], 16;\n" :: "r"(dst), "l"(src));
}
__device__ __forceinline__ void cp16s(uint32_t dst, const void* src) {
    asm volatile("cp.async.cg.shared.global [%0], [%1], 16;\n" :: "r"(dst), "l"(src));
}
__device__ __forceinline__ void cpcommit() {
    asm volatile("cp.async.commit_group;\n");
}
#define CPWAIT(n) asm volatile("cp.async.wait_group %0;\n" :: "n"(n) : "memory")

__device__ __forceinline__ void mma_f16(float* c, uint32_t a0, uint32_t a1,
                                        uint32_t a2, uint32_t a3,
                                        uint32_t b0, uint32_t b1) {
    asm volatile(
        "mma.sync.aligned.m16n8k16.row.col.f32.f16.f16.f32 "
        "{%0,%1,%2,%3}, {%4,%5,%6,%7}, {%8,%9}, {%0,%1,%2,%3};"
        : "+f"(c[0]), "+f"(c[1]), "+f"(c[2]), "+f"(c[3])
        : "r"(a0), "r"(a1), "r"(a2), "r"(a3), "r"(b0), "r"(b1));
}

// ---------------------------------------------------------------------------
__global__ void prep_kernel(const float* __restrict__ w1,
                            const float* __restrict__ w2,
                            const float* __restrict__ w3) {
    int s = blockIdx.x * blockDim.x + threadIdx.x;   // 0..9215
    if (s >= 9216) return;
    int lane = s & 31;
    int g = lane >> 2, t4 = lane & 3;
    if (s < 4096) {     // w1 (B-frag): [ch16][nb8][lane]
        int nb = (s >> 5) & 7, ch = s >> 8;
        int oc = nb * 8 + g, k0 = ch * 16 + 2 * t4;
        const float* wp = w1 + oc * CIN_ + k0;
        uint2 v;
        v.x = pack2(wp[0], wp[1]);
        v.y = pack2(wp[8], wp[9]);
        g_w1b[s] = v;
    }
    if (s < 2048) {     // w3 (A-frag): [ch4][mb16][lane]
        int mb = (s >> 5) & 15, ch = s >> 9;
        int row = mb * 16 + g, k0 = ch * 16 + 2 * t4;
        uint4 v;
        v.x = pack2(w3[row * MID_ + k0],           w3[row * MID_ + k0 + 1]);
        v.y = pack2(w3[(row + 8) * MID_ + k0],     w3[(row + 8) * MID_ + k0 + 1]);
        v.z = pack2(w3[row * MID_ + k0 + 8],       w3[row * MID_ + k0 + 9]);
        v.w = pack2(w3[(row + 8) * MID_ + k0 + 8], w3[(row + 8) * MID_ + k0 + 9]);
        g_w3a[s] = v;
    }
    {                   // w2 (B-frag): [ch4][tap9][nb8][lane]
        int nb = (s >> 5) & 7;
        int tap = (s % 2304) >> 8;
        int ch = s / 2304;
        int oc = nb * 8 + g, ic0 = ch * 16 + 2 * t4;
        const float* wp = w2 + ((size_t)oc * MID_ + ic0) * 9 + tap;
        uint2 v;
        v.x = pack2(wp[0], wp[9]);
        v.y = pack2(wp[8 * 9], wp[9 * 9]);
        g_w2b[s] = v;
    }
}

// ---------------------------------------------------------------------------
__global__ void gate_kernel(const float* __restrict__ emb,
                            const float* __restrict__ gw,
                            const float* __restrict__ gb,
                            float* __restrict__ out_tail) {
    int idx = blockIdx.x * blockDim.x + threadIdx.x;
    if (idx >= B_ * MID_) return;
    int b = idx / MID_, c = idx % MID_;
    const float* e = emb + b * EMB_;
    const float* w = gw + c * EMB_;
    float acc = gb[c];
#pragma unroll 8
    for (int k = 0; k < EMB_; k++) acc = fmaf(e[k], w[k], acc);
    acc = fmaxf(acc, 0.f);
    g_gate[idx] = acc;
    out_tail[idx] = acc;
}

// ---------------------------------------------------------------------------
// conv1: M=256px, N=64oc, K=256. 4-buffer / 3-in-flight cp.async pipeline
// (dyn smem 74752B -> 3 blocks/SM). grid (49, 16) per half.
// ---------------------------------------------------------------------------
__global__ __launch_bounds__(256) void conv1_kernel(
    const float* __restrict__ x,
    const float* __restrict__ bg, const float* __restrict__ bb,
    const float* __restrict__ bm, const float* __restrict__ bv,
    int bbase) {
    extern __shared__ char dsm[];
    float (*Xs)[16][260] = (float(*)[16][260])dsm;              // 4 x 16640
    uint2 (*Wb)[8][32]   = (uint2(*)[8][32])(dsm + 66560);      // 4 x 2048
    const int b   = blockIdx.y + bbase;
    const int p0  = blockIdx.x * 256;
    const int tid = threadIdx.x;
    const int lane = tid & 31, w = tid >> 5;
    const int g = lane >> 2, t4 = lane & 3;
    const int pw = w * 32;
    const float* xb = x + (size_t)b * CIN_ * HW_ + p0;

    float c[2][8][4];
#pragma unroll
    for (int mi = 0; mi < 2; mi++)
#pragma unroll
        for (int nb = 0; nb < 8; nb++)
#pragma unroll
            for (int q = 0; q < 4; q++) c[mi][nb][q] = 0.f;

    auto stage = [&](int ch) {
        int buf = ch & 3;
        if (tid < 128)
            cp16(sa(((uint2*)Wb[buf]) + tid * 2), g_w1b + ch * 256 + tid * 2);
#pragma unroll
        for (int i = 0; i < 4; i++) {
            int e4 = tid + i * 256;
            int kk = e4 >> 6, c4 = e4 & 63;
            cp16s(sa(&Xs[buf][kk][c4 * 4]),
                  xb + (size_t)(ch * 16 + kk) * HW_ + c4 * 4);
        }
        cpcommit();
    };

    stage(0); stage(1); stage(2);

    for (int ch = 0; ch < 16; ch++) {
        const int buf = ch & 3;
        const int rem = 15 - ch;
        if (rem >= 2)      { CPWAIT(2); }
        else if (rem == 1) { CPWAIT(1); }
        else               { CPWAIT(0); }
        __syncthreads();
        if (ch + 3 < 16) stage(ch + 3);

        uint32_t a[2][4];
#pragma unroll
        for (int mi = 0; mi < 2; mi++) {
            int p = pw + mi * 16 + g;
            a[mi][0] = pack2(Xs[buf][2*t4][p],     Xs[buf][2*t4+1][p]);
            a[mi][1] = pack2(Xs[buf][2*t4][p+8],   Xs[buf][2*t4+1][p+8]);
            a[mi][2] = pack2(Xs[buf][2*t4+8][p],   Xs[buf][2*t4+9][p]);
            a[mi][3] = pack2(Xs[buf][2*t4+8][p+8], Xs[buf][2*t4+9][p+8]);
        }
#pragma unroll
        for (int nb = 0; nb < 8; nb++) {
            uint2 bf = Wb[buf][nb][lane];
#pragma unroll
            for (int mi = 0; mi < 2; mi++)
                mma_f16(c[mi][nb], a[mi][0], a[mi][1], a[mi][2], a[mi][3],
                        bf.x, bf.y);
        }
    }
#pragma unroll
    for (int nb = 0; nb < 8; nb++) {
        int oc = nb * 8 + 2 * t4;
        float ie = rsqrtf(bv[oc] + EPS_) * bg[oc];
        float be = bb[oc] - bm[oc] * ie;
        float io = rsqrtf(bv[oc+1] + EPS_) * bg[oc+1];
        float bo = bb[oc+1] - bm[oc+1] * io;
        uint32_t* base = g_t1p2 + (size_t)(b * 32 + nb * 4 + t4) * PR_ * PC_;
#pragma unroll
        for (int mi = 0; mi < 2; mi++) {
#pragma unroll
            for (int h = 0; h < 2; h++) {
                int p = p0 + pw + mi * 16 + g + h * 8;
                int y = p / W_, xx = p % W_;
                float ve = fmaxf(fmaf(c[mi][nb][2*h],   ie, be), 0.f);
                float vo = fmaxf(fmaf(c[mi][nb][2*h+1], io, bo), 0.f);
                base[(size_t)(y + 1) * PC_ + xx + 1] = pack2(ve, vo);
            }
        }
    }
}

// ---------------------------------------------------------------------------
// conv2: tensor-bound, unchanged. grid (7,7,16) per half.
// ---------------------------------------------------------------------------
__global__ __launch_bounds__(256) void conv2_kernel(
    const float* __restrict__ bg, const float* __restrict__ bb,
    const float* __restrict__ bm, const float* __restrict__ bv,
    int bbase) {
    extern __shared__ char dsm[];
    uint2    (*Wb)[9][8][32] = (uint2(*)[9][8][32])dsm;                // 2x18432
    uint32_t (*Xh)           = (uint32_t*)(dsm + 36864);               // 2x14080
    const int b   = blockIdx.z + bbase;
    const int ry0 = blockIdx.y * 16;
    const int cx0 = blockIdx.x * 16;
    const int tid = threadIdx.x;
    const int lane = tid & 31, w = tid >> 5;
    const int g = lane >> 2, t4 = lane & 3;
    const int ICS = 440;

    float c[2][8][4];
#pragma unroll
    for (int mi = 0; mi < 2; mi++)
#pragma unroll
        for (int nb = 0; nb < 8; nb++)
#pragma unroll
            for (int q = 0; q < 4; q++) c[mi][nb][q] = 0.f;

    auto stage = [&](int ch, int buf) {
#pragma unroll
        for (int i = 0; i < 5; i++) {
            int e = tid + i * 256;
            if (e < 1152)
                cp16(sa(((uint2*)Wb[buf]) + e * 2), g_w2b + ch * 2304 + e * 2);
        }
        uint32_t* hb = Xh + buf * 3520;
#pragma unroll
        for (int i = 0; i < 4; i++) {
            int e = tid + i * 256;
            if (e < 864) {
                int icp = e / 108, rem = e % 108;
                int r = rem / 6, c6 = rem % 6;
                const uint32_t* src = g_t1p2 +
                    ((size_t)(b * 32 + ch * 8 + icp) * PR_ + ry0 + r) * PC_
                    + cx0 + c6 * 4;
                cp16s(sa(hb + icp * ICS + r * 24 + c6 * 4), src);
            }
        }
        cpcommit();
    };

    stage(0, 0);
    CPWAIT(0);
    __syncthreads();

    for (int ch = 0; ch < 4; ch++) {
        const int cur = ch & 1;
        if (ch + 1 < 4) stage(ch + 1, cur ^ 1);
        const uint32_t* hb = Xh + cur * 3520;
#pragma unroll
        for (int t = 0; t < 9; t++) {
            const int ky = t / 3, kx = t % 3;
            uint2 bf[8];
#pragma unroll
            for (int nb = 0; nb < 8; nb++) bf[nb] = Wb[cur][t][nb][lane];
#pragma unroll
            for (int mi = 0; mi < 2; mi++) {
                int r = 2 * w + mi + ky;
                const uint32_t* h0 = hb + t4 * ICS + r * 24 + g + kx;
                const uint32_t* h1 = hb + (t4 + 4) * ICS + r * 24 + g + kx;
                uint32_t a0 = h0[0], a1 = h0[8], a2 = h1[0], a3 = h1[8];
#pragma unroll
                for (int nb = 0; nb < 8; nb++)
                    mma_f16(c[mi][nb], a0, a1, a2, a3, bf[nb].x, bf[nb].y);
            }
        }
        CPWAIT(0);
        __syncthreads();
    }
#pragma unroll
    for (int nb = 0; nb < 8; nb++) {
        int oc = nb * 8 + 2 * t4;
        float ge = g_gate[b * MID_ + oc];
        float go = g_gate[b * MID_ + oc + 1];
        float ie = rsqrtf(bv[oc] + EPS_) * bg[oc];
        float be = bb[oc] - bm[oc] * ie;
        float io = rsqrtf(bv[oc+1] + EPS_) * bg[oc+1];
        float bo = bb[oc+1] - bm[oc+1] * io;
        uint32_t* base = g_t2p2 + (size_t)(b * 32 + nb * 4 + t4) * HW_;
#pragma unroll
        for (int mi = 0; mi < 2; mi++) {
            int y = ry0 + 2 * w + mi;
#pragma unroll
            for (int h = 0; h < 2; h++) {
                int xx = cx0 + g + h * 8;
                float ve = fmaxf(fmaf(c[mi][nb][2*h]   * ge, ie, be), 0.f);
                float vo = fmaxf(fmaf(c[mi][nb][2*h+1] * go, io, bo), 0.f);
                base[y * W_ + xx] = pack2(ve, vo);
            }
        }
    }
}

// ---------------------------------------------------------------------------
// conv3 (swapped roles): block 128oc x 128px, M=oc, N=px, K=64.
// 8 warps = 2 ocg x 4 pxg (warp m64 x n32). float2 stores + float2 identity.
// All K staged up-front; identity streamed under MMA. dyn smem 103424B.
// grid (98, 2, 16) per half.
// ---------------------------------------------------------------------------
__global__ __launch_bounds__(256) void conv3_kernel(
    const float* __restrict__ x,
    const float* __restrict__ bg, const float* __restrict__ bb,
    const float* __restrict__ bm, const float* __restrict__ bv,
    float* __restrict__ out, int bbase) {
    extern __shared__ char dsm[];
    uint4    (*Wa)[8][32]  = (uint4(*)[8][32])dsm;               // 4x4096 = 16384
    uint32_t (*A2)[8][136] = (uint32_t(*)[8][136])(dsm + 16384); // 4x4352 = 17408
    float*   Xid           = (float*)(dsm + 33792);              // 128x136x4 = 69632
    const int b   = blockIdx.z + bbase;
    const int oc0 = blockIdx.y * 128;
    const int p0  = blockIdx.x * 128;
    const int tid = threadIdx.x;
    const int lane = tid & 31, w = tid >> 5;
    const int ocg = w >> 2, pxg = w & 3;
    const int g = lane >> 2, t4 = lane & 3;
    const uint32_t* t2b = g_t2p2 + (size_t)b * 32 * HW_ + p0;
    const float* xg = x + ((size_t)b * CIN_ + oc0) * HW_ + p0;
    const int mb0 = oc0 >> 4;              // 0 or 8

    float c[4][4][4];
#pragma unroll
    for (int mi = 0; mi < 4; mi++)
#pragma unroll
        for (int nb = 0; nb < 4; nb++)
#pragma unroll
            for (int q = 0; q < 4; q++) c[mi][nb][q] = 0.f;

    // group 0: all weights (A-frags) + all t2 (B)
    {
#pragma unroll
        for (int i = 0; i < 4; i++) {
            int e = tid + i * 256;               // 0..1023
            int ch = e >> 8, mb = (e >> 5) & 7, ln = e & 31;
            cp16(sa(&Wa[ch][mb][ln]),
                 g_w3a + ch * 512 + (mb0 + mb) * 32 + ln);
        }
#pragma unroll
        for (int i = 0; i < 4; i++) {
            int e = tid + i * 256;               // 0..1023
            int ch = e >> 8, kp = (e >> 5) & 7, c8 = e & 31;
            cp16s(sa(&A2[ch][kp][c8 * 4]),
                  t2b + (size_t)(ch * 8 + kp) * HW_ + c8 * 4);
        }
        cpcommit();
    }
    // groups 1..4: identity 128oc x 128px fp32, smem row stride 136
#pragma unroll
    for (int grp = 0; grp < 4; grp++) {
#pragma unroll
        for (int i = 0; i < 4; i++) {
            int e = tid + (grp * 4 + i) * 256;   // 0..4095
            int oc = e >> 5, c8 = e & 31;
            cp16s(sa(Xid + oc * 136 + c8 * 4),
                  xg + (size_t)oc * HW_ + c8 * 4);
        }
        cpcommit();
    }

    CPWAIT(4);            // weights + t2 ready; identity still streaming
    __syncthreads();

#pragma unroll
    for (int ch = 0; ch < 4; ch++) {
        uint4 af[4];
#pragma unroll
        for (int mi = 0; mi < 4; mi++)
            af[mi] = Wa[ch][ocg * 4 + mi][lane];
#pragma unroll
        for (int nb = 0; nb < 4; nb++) {
            int pxl = pxg * 32 + nb * 8 + g;
            uint32_t b0 = A2[ch][t4][pxl];
            uint32_t b1 = A2[ch][t4 + 4][pxl];
#pragma unroll
            for (int mi = 0; mi < 4; mi++)
                mma_f16(c[mi][nb], af[mi].x, af[mi].y, af[mi].z, af[mi].w,
                        b0, b1);
        }
    }

    CPWAIT(0);            // identity landed
    __syncthreads();

    // epilogue: bn + identity (smem, float2) + relu, float2 stores
#pragma unroll
    for (int mi = 0; mi < 4; mi++) {
#pragma unroll
        for (int r = 0; r < 2; r++) {
            int ocl = ocg * 64 + mi * 16 + g + r * 8;
            int oc  = oc0 + ocl;
            float iv = rsqrtf(bv[oc] + EPS_) * bg[oc];
            float bs = bb[oc] - bm[oc] * iv;
            float* op = out + ((size_t)b * CIN_ + oc) * HW_ + p0;
            const float* sp = Xid + ocl * 136;
#pragma unroll
            for (int nb = 0; nb < 4; nb++) {
                int px = pxg * 32 + nb * 8 + 2 * t4;
                float2 id = *(const float2*)&sp[px];
                float2 v;
                v.x = fmaxf(fmaf(c[mi][nb][2*r],     iv, bs) + id.x, 0.f);
                v.y = fmaxf(fmaf(c[mi][nb][2*r + 1], iv, bs) + id.y, 0.f);
                *(float2*)&op[px] = v;
            }
        }
    }
}

// ---------------------------------------------------------------------------
static cudaStream_t g_s1 = nullptr;
static cudaEvent_t  g_evA = nullptr, g_evB = nullptr;
static bool g_pipe_ok = false;
static struct _StreamInit {
    _StreamInit() {
        g_pipe_ok =
            cudaStreamCreateWithFlags(&g_s1, cudaStreamNonBlocking) == cudaSuccess &&
            cudaEventCreateWithFlags(&g_evA, cudaEventDisableTiming) == cudaSuccess &&
            cudaEventCreateWithFlags(&g_evB, cudaEventDisableTiming) == cudaSuccess;
    }
} _stream_init;

extern "C" void kernel_launch(void* const* d_in, const int* in_sizes, int n_in,
                              void* d_out, int out_size) {
    const float* x     = (const float*)d_in[0];
    const float* emb   = (const float*)d_in[1];
    const float* w1    = (const float*)d_in[2];
    const float* bn1_g = (const float*)d_in[3];
    const float* bn1_b = (const float*)d_in[4];
    const float* bn1_m = (const float*)d_in[5];
    const float* bn1_v = (const float*)d_in[6];
    const float* w2    = (const float*)d_in[7];
    const float* bn2_g = (const float*)d_in[8];
    const float* bn2_b = (const float*)d_in[9];
    const float* bn2_m = (const float*)d_in[10];
    const float* bn2_v = (const float*)d_in[11];
    const float* w3    = (const float*)d_in[12];
    const float* bn3_g = (const float*)d_in[13];
    const float* bn3_b = (const float*)d_in[14];
    const float* bn3_m = (const float*)d_in[15];
    const float* bn3_v = (const float*)d_in[16];
    const float* gw    = (const float*)d_in[17];
    const float* gb    = (const float*)d_in[18];
    float* out = (float*)d_out;

    cudaFuncSetAttribute(conv1_kernel,
                         cudaFuncAttributeMaxDynamicSharedMemorySize, 74752);
    cudaFuncSetAttribute(conv2_kernel,
                         cudaFuncAttributeMaxDynamicSharedMemorySize, 65024);
    cudaFuncSetAttribute(conv3_kernel,
                         cudaFuncAttributeMaxDynamicSharedMemorySize, 103424);

    const int HB = B_ / 2;                 // 16 batches per half
    dim3 g1(HW_ / 256, HB);
    dim3 g2(W_ / 16, H_ / 16, HB);
    dim3 g3(HW_ / 128, 2, HB);

    prep_kernel<<<36, 256>>>(w1, w2, w3);
    gate_kernel<<<(B_ * MID_ + 255) / 256, 256>>>(emb, gw, gb, out + OUT_MAIN_);

    if (g_pipe_ok) {
        conv1_kernel<<<g1, 256, 74752>>>(x, bn1_g, bn1_b, bn1_m, bn1_v, 0);
        cudaEventRecord(g_evA, 0);
        cudaStreamWaitEvent(g_s1, g_evA, 0);
        conv1_kernel<<<g1, 256, 74752, g_s1>>>(x, bn1_g, bn1_b, bn1_m, bn1_v, HB);
        conv2_kernel<<<g2, 256, 65024>>>(bn2_g, bn2_b, bn2_m, bn2_v, 0);
        conv2_kernel<<<g2, 256, 65024, g_s1>>>(bn2_g, bn2_b, bn2_m, bn2_v, HB);
        conv3_kernel<<<g3, 256, 103424>>>(x, bn3_g, bn3_b, bn3_m, bn3_v, out, 0);
        conv3_kernel<<<g3, 256, 103424, g_s1>>>(x, bn3_g, bn3_b, bn3_m, bn3_v, out, HB);
        cudaEventRecord(g_evB, g_s1);
        cudaStreamWaitEvent(0, g_evB, 0);
    } else {
        conv1_kernel<<<g1, 256, 74752>>>(x, bn1_g, bn1_b, bn1_m, bn1_v, 0);
        conv1_kernel<<<g1, 256, 74752>>>(x, bn1_g, bn1_b, bn1_m, bn1_v, HB);
        conv2_kernel<<<g2, 256, 65024>>>(bn2_g, bn2_b, bn2_m, bn2_v, 0);
        conv2_kernel<<<g2, 256, 65024>>>(bn2_g, bn2_b, bn2_m, bn2_v, HB);
        conv3_kernel<<<g3, 256, 103424>>>(x, bn3_g, bn3_b, bn3_m, bn3_v, out, 0);
        conv3_kernel<<<g3, 256, 103424>>>(x, bn3_g, bn3_b, bn3_m, bn3_v, out, HB);
    }
}